// round 14
// baseline (speedup 1.0000x reference)
#include <cuda_runtime.h>
#include <cuda_bf16.h>
#include <math.h>
#include <stdint.h>

#define Ng 96
#define nS 48
#define RK 16
#define Dd 128
#define Cc 10
#define NSS 1176   // 48*49/2 graph-pair tiles (2x2 graphs per tile)
#define NST 2304   // 48*48
#define TPB 384    // threads per tile block (12 warps: 2 x 6)

// tile-kernel smem layout in u32 units
#define LDU 68
#define LDB 272
#define AH_U 0
#define AL_U (96 * LDU)
#define BH_U (2 * 96 * LDU)
#define BL_U (3 * 96 * LDU)
#define DV_U (4 * 96 * LDU)          // 6 x 96 floats: eA,A1,A2,eB,B1,B2
#define WS_U (DV_U + 576)
#define SMEM_U32 (WS_U + 16)
#define SMEM_BYTES (SMEM_U32 * 4)

// ---------- persistent scratch ----------
__device__ float g_es[Ng * nS];   // 0.01 / d0S
__device__ float g_wd[Ng * nS];   // w * d0S
__device__ float g_w[Ng * nS];    // w
__device__ float g_et[Ng * nS];   // 0.01 / d0T
__device__ float g_zd[Ng * nS];   // z * d0T
__device__ float g_z[Ng * nS];    // z
__device__ float g_KST[Ng * Ng];
__device__ float g_alpha[Ng * Cc];
__device__ __nv_bfloat16 g_Shi[Ng * nS * Dd];   // normalized x/d0, hi
__device__ __nv_bfloat16 g_Slo[Ng * nS * Dd];
__device__ __nv_bfloat16 g_Thi[Ng * nS * Dd];
__device__ __nv_bfloat16 g_Tlo[Ng * nS * Dd];

// ---------- streams/events (static init) ----------
namespace {
struct GpuRes {
    cudaStream_t s2;
    cudaEvent_t evSS, evSolve;
    GpuRes() {
        cudaStreamCreateWithFlags(&s2, cudaStreamNonBlocking);
        cudaEventCreateWithFlags(&evSS, cudaEventDisableTiming);
        cudaEventCreateWithFlags(&evSolve, cudaEventDisableTiming);
    }
};
GpuRes g_res;
}

// ---------- mma.sync m16n8k16 bf16 ----------
__device__ __forceinline__ void mma16816(float* c, uint32_t a0, uint32_t a1,
                                         uint32_t a2, uint32_t a3,
                                         uint32_t b0, uint32_t b1) {
    asm volatile(
        "mma.sync.aligned.m16n8k16.row.col.f32.bf16.bf16.f32 "
        "{%0,%1,%2,%3}, {%4,%5,%6,%7}, {%8,%9}, {%0,%1,%2,%3};"
        : "+f"(c[0]), "+f"(c[1]), "+f"(c[2]), "+f"(c[3])
        : "r"(a0), "r"(a1), "r"(a2), "r"(a3), "r"(b0), "r"(b1));
}
__device__ __forceinline__ void ldmx4(uint32_t* r, uint32_t addr) {
    asm volatile("ldmatrix.sync.aligned.m8n8.x4.shared.b16 {%0,%1,%2,%3}, [%4];"
                 : "=r"(r[0]), "=r"(r[1]), "=r"(r[2]), "=r"(r[3]) : "r"(addr));
}
__device__ __forceinline__ uint32_t smem_u32(const void* p) {
    uint32_t a;
    asm("{ .reg .u64 t; cvta.to.shared.u64 t, %1; cvt.u32.u64 %0, t; }"
        : "=r"(a) : "l"(p));
    return a;
}

// ---------- fast NTK (normalized form; acos poly A&S 4.4.46) ----------
__device__ __forceinline__ float acos_pos(float ax, float u) {
    float p = fmaf(ax, -0.0012624911f, 0.0066700901f);
    p = fmaf(ax, p, -0.0170881256f);
    p = fmaf(ax, p, 0.0308918810f);
    p = fmaf(ax, p, -0.0501743046f);
    p = fmaf(ax, p, 0.0889789874f);
    p = fmaf(ax, p, -0.2145988016f);
    p = fmaf(ax, p, 1.5707963050f);
    return u * p;
}

__device__ __forceinline__ float ntk_acc(float p, float dot, float ea, float eb,
                                         float ab1, float ab2, float ic1) {
    const float PI_F = 3.14159265358979323846f;
    const float IPI = 0.318309886183790672f;
    float sir = fmaf(ea, eb, dot);
    float si = fminf(fmaxf(sir, -0.9999f), 0.9999f);
    float ax = fabsf(si);
    float u = sqrtf(1.f - ax);
    float vq = sqrtf(1.f + ax);
    float thp = acos_pos(ax, u);
    float pit = (si < 0.f) ? thp : (PI_F - thp);
    float D1 = pit * IPI;
    float s1 = fmaf(si, pit, u * vq) * IPI;
    float si2 = fminf(s1 * ic1, 0.9999f);
    float u2 = sqrtf(1.f - si2);
    float v2 = sqrtf(1.f + si2);
    float pit2 = PI_F - acos_pos(si2, u2);
    float D2 = pit2 * IPI;
    float s2v = fmaf(si2, pit2, u2 * v2) * IPI;
    p = fmaf(ab1 * sir, D1 * D2, p);
    p = fmaf(ab2, fmaf(s1, D2, s2v), p);
    return p;
}

// ============================================================
// Kernel A: per-graph precompute
// ============================================================
__global__ void precompute_kernel(const float* __restrict__ U,
                                  const float* __restrict__ V,
                                  const float* __restrict__ XS,
                                  const float* __restrict__ AT,
                                  const float* __restrict__ XT) {
    int g = blockIdx.x, t = threadIdx.x;
    __shared__ float sU[nS * RK];
    __shared__ float sV[RK * nS];
    __shared__ float sA[nS * nS];
    __shared__ float VU[RK][RK];
    __shared__ float u1[RK], u2a[RK], u2[RK], sv[nS];
    __shared__ float d0s[nS], d0t[nS], invs[nS], invt[nS];

    const float4* Up = (const float4*)(U + (size_t)g * nS * RK);
    const float4* Vp = (const float4*)(V + (size_t)g * RK * nS);
    const float4* Ap = (const float4*)(AT + (size_t)g * nS * nS);
    for (int i = t; i < 192; i += 128) ((float4*)sU)[i] = Up[i];
    for (int i = t; i < 192; i += 128) ((float4*)sV)[i] = Vp[i];
    for (int i = t; i < 576; i += 128) ((float4*)sA)[i] = Ap[i];

    const float* xs = XS + (size_t)g * nS * Dd;
    const float* xt = XT + (size_t)g * nS * Dd;
    if (t < nS) {
        const float4* row = (const float4*)(xs + t * Dd);
        float acc = 0.f;
        #pragma unroll
        for (int k = 0; k < Dd / 4; k++) {
            float4 v = row[k];
            acc += v.x * v.x + v.y * v.y + v.z * v.z + v.w * v.w;
        }
        float d = sqrtf(acc + 1e-4f);
        d0s[t] = d;
        invs[t] = 1.f / d;
    } else if (t < 2 * nS) {
        int r = t - nS;
        const float4* row = (const float4*)(xt + r * Dd);
        float acc = 0.f;
        #pragma unroll
        for (int k = 0; k < Dd / 4; k++) {
            float4 v = row[k];
            acc += v.x * v.x + v.y * v.y + v.z * v.z + v.w * v.w;
        }
        float d = sqrtf(acc + 1e-4f);
        d0t[r] = d;
        invt[r] = 1.f / d;
    }
    __syncthreads();

    {
        const float4* xs4 = (const float4*)xs;
        const float4* xt4 = (const float4*)xt;
        size_t base = (size_t)g * nS * Dd / 4;
        for (int i = t; i < nS * 32; i += 128) {
            int row = i >> 5;
            float4 a = xs4[i];
            float is = invs[row];
            __nv_bfloat16 hh[4], ll[4];
            float av[4] = {a.x * is, a.y * is, a.z * is, a.w * is};
            #pragma unroll
            for (int e = 0; e < 4; e++) {
                __nv_bfloat16 h = __float2bfloat16(av[e]);
                hh[e] = h;
                ll[e] = __float2bfloat16(av[e] - __bfloat162float(h));
            }
            ((uint2*)g_Shi)[base + i] = *(uint2*)hh;
            ((uint2*)g_Slo)[base + i] = *(uint2*)ll;

            float4 b = xt4[i];
            float it = invt[row];
            float bv[4] = {b.x * it, b.y * it, b.z * it, b.w * it};
            #pragma unroll
            for (int e = 0; e < 4; e++) {
                __nv_bfloat16 h = __float2bfloat16(bv[e]);
                hh[e] = h;
                ll[e] = __float2bfloat16(bv[e] - __bfloat162float(h));
            }
            ((uint2*)g_Thi)[base + i] = *(uint2*)hh;
            ((uint2*)g_Tlo)[base + i] = *(uint2*)ll;
        }
    }
    __syncthreads();

    for (int e = t; e < RK * RK; e += 128) {
        int i = e >> 4, jj = e & 15;
        float acc = 0.f;
        #pragma unroll 8
        for (int a = 0; a < nS; a++) acc += sV[i * nS + a] * sU[a * RK + jj];
        VU[i][jj] = acc;
    }
    if (t < RK) {
        float acc = 0.f;
        #pragma unroll 8
        for (int a = 0; a < nS; a++) acc += sU[a * RK + t];
        u1[t] = acc;
    } else if (t >= 32 && t < 32 + nS) {
        int i = t - 32;
        float acc = 0.f;
        #pragma unroll 8
        for (int jj = 0; jj < nS; jj++) acc += sA[jj * nS + i];
        sv[i] = acc + 1e-4f;
    }
    __syncthreads();
    if (t < RK) {
        float acc = 0.f;
        #pragma unroll
        for (int r = 0; r < RK; r++) acc += VU[r][t] * u1[r];
        u2a[t] = acc;
    }
    __syncthreads();
    if (t < RK) {
        float acc = 0.f;
        #pragma unroll
        for (int r = 0; r < RK; r++) acc += VU[r][t] * u2a[r];
        u2[t] = acc;
    }
    __syncthreads();
    if (t < nS) {
        float acc = 0.f;
        #pragma unroll
        for (int r = 0; r < RK; r++) acc += sV[r * nS + t] * u2[r];
        g_w[g * nS + t] = acc;
        g_wd[g * nS + t] = acc * d0s[t];
        g_es[g * nS + t] = 0.01f * invs[t];
    } else if (t < 2 * nS) {
        int i = t - nS;
        float acc = 0.f;
        #pragma unroll 8
        for (int jj = 0; jj < nS; jj++) acc += sA[jj * nS + i] * sv[jj];
        float z = acc + 1e-4f * sv[i];
        g_z[g * nS + i] = z;
        g_zd[g * nS + i] = z * d0t[i];
        g_et[g * nS + i] = 0.01f * invt[i];
    }
}

// ============================================================
// Kernel B: HMMA tile kernel, 384 threads (12 warps, 2x6 grid,
// warp tile 48x16, 24 accums/thread). mode 0 = SS, 1 = ST.
// ============================================================
__global__ void __launch_bounds__(TPB, 2)
mma_tile_kernel(float* __restrict__ KSS, int mode) {
    extern __shared__ uint32_t smU[];
    int bid = blockIdx.x;

    int ti, tj, isST = mode;
    if (!mode) {
        int rem = bid, cnt = 48;
        ti = 0;
        while (rem >= cnt) { rem -= cnt; ti++; cnt--; }
        tj = ti + rem;
    } else {
        ti = bid / 48;
        tj = bid - ti * 48;
    }

    uint32_t sbase = smem_u32(smU);
    int t = threadIdx.x;
    int w = t >> 5, lane = t & 31;
    int g2 = lane >> 2, tg = lane & 3;

    const uint4* ShiV = (const uint4*)g_Shi;
    const uint4* SloV = (const uint4*)g_Slo;
    const uint4* RhiV = isST ? (const uint4*)g_Thi : ShiV;
    const uint4* RloV = isST ? (const uint4*)g_Tlo : SloV;
    int rowL = ti * 96, rowR = tj * 96;

    for (int idx = t; idx < 96 * 16; idx += TPB) {
        int r = idx >> 4, c4 = idx & 15;
        int so = r * LDU + c4 * 4;
        *(uint4*)(smU + AH_U + so) = ShiV[(size_t)(rowL + r) * 16 + c4];
        *(uint4*)(smU + AL_U + so) = SloV[(size_t)(rowL + r) * 16 + c4];
        *(uint4*)(smU + BH_U + so) = RhiV[(size_t)(rowR + r) * 16 + c4];
        *(uint4*)(smU + BL_U + so) = RloV[(size_t)(rowR + r) * 16 + c4];
    }
    float* dv = (float*)(smU + DV_U);
    if (t < 96) {
        dv[t] = g_es[rowL + t];
        dv[96 + t] = g_wd[rowL + t];
        dv[192 + t] = g_w[rowL + t];
    } else if (t < 192) {
        int r = t - 96;
        dv[288 + r] = (isST ? g_et : g_es)[rowR + r];
        dv[384 + r] = (isST ? g_zd : g_wd)[rowR + r];
        dv[480 + r] = (isST ? g_z : g_w)[rowR + r];
    }
    __syncthreads();

    // warp (wr, wc): rows [wr*48, +48), cols [wc*16, +16)
    int wr = w / 6, wc = w - wr * 6;
    int mrow0 = wr * 48, ncol0 = wc * 16;

    int l7 = lane & 7;
    uint32_t aoff = (uint32_t)((mrow0 + l7 + ((lane >> 3) & 1) * 8) * LDB +
                               ((lane >> 4) & 1) * 16);
    uint32_t boff = (uint32_t)((ncol0 + ((lane >> 4) & 1) * 8 + l7) * LDB +
                               ((lane >> 3) & 1) * 16);

    float acc[3][2][4];
    #pragma unroll
    for (int mi = 0; mi < 3; mi++)
        #pragma unroll
        for (int nj = 0; nj < 2; nj++)
            #pragma unroll
            for (int e = 0; e < 4; e++) acc[mi][nj][e] = 0.f;

    #pragma unroll
    for (int s = 0; s < 3; s++) {
        uint32_t Ab = sbase + (uint32_t)((s == 2 ? AL_U : AH_U) * 4);
        uint32_t Bb = sbase + (uint32_t)((s == 1 ? BL_U : BH_U) * 4);
        #pragma unroll
        for (int ks = 0; ks < 8; ks++) {
            uint32_t kb = (uint32_t)(ks * 32);
            uint32_t b01[4];
            ldmx4(b01, Bb + boff + kb);
            #pragma unroll
            for (int mi = 0; mi < 3; mi++) {
                uint32_t a[4];
                ldmx4(a, Ab + aoff + (uint32_t)(mi * 16 * LDB) + kb);
                mma16816(acc[mi][0], a[0], a[1], a[2], a[3], b01[0], b01[1]);
                mma16816(acc[mi][1], a[0], a[1], a[2], a[3], b01[2], b01[3]);
            }
        }
    }

    const float PI_F = 3.14159265358979323846f;
    float thc = acosf(0.9999f);
    float c1 = (0.9999f * (PI_F - thc) + sqrtf(1.f - 0.9999f * 0.9999f)) / PI_F;
    float ic1 = 1.f / c1;

    const float* sEa = dv;
    const float* sA1 = dv + 96;
    const float* sA2 = dv + 192;
    const float* sEb = dv + 288;
    const float* sB1 = dv + 384;
    const float* sB2 = dv + 480;

    float partial = 0.f;
    #pragma unroll
    for (int mi = 0; mi < 3; mi++) {
        int r0 = mrow0 + mi * 16 + g2, r1 = r0 + 8;
        float ea0 = sEa[r0], a10 = sA1[r0], a20 = sA2[r0];
        float ea1 = sEa[r1], a11 = sA1[r1], a21 = sA2[r1];
        #pragma unroll
        for (int nj = 0; nj < 2; nj++) {
            int c0 = ncol0 + nj * 8 + tg * 2, c1i = c0 + 1;
            float eb0 = sEb[c0], b10 = sB1[c0], b20 = sB2[c0];
            float eb1 = sEb[c1i], b11 = sB1[c1i], b21 = sB2[c1i];
            partial = ntk_acc(partial, acc[mi][nj][0], ea0, eb0, a10 * b10, a20 * b20, ic1);
            partial = ntk_acc(partial, acc[mi][nj][1], ea0, eb1, a10 * b11, a20 * b21, ic1);
            partial = ntk_acc(partial, acc[mi][nj][2], ea1, eb0, a11 * b10, a21 * b20, ic1);
            partial = ntk_acc(partial, acc[mi][nj][3], ea1, eb1, a11 * b11, a21 * b21, ic1);
        }
    }

    #pragma unroll
    for (int o = 16; o > 0; o >>= 1)
        partial += __shfl_down_sync(0xffffffffu, partial, o);
    float* wslot = (float*)(smU + WS_U);
    if (lane == 0) wslot[w] = partial;
    __syncthreads();

    // quadrant (qi, qj): warps {qi*6 + qj*3 + 0..2}
    if (t < 4) {
        int qi = t >> 1, qj = t & 1;
        int w0 = qi * 6 + qj * 3;
        float s = wslot[w0] + wslot[w0 + 1] + wslot[w0 + 2];
        int N = 2 * ti + qi, M = 2 * tj + qj;
        if (!isST) {
            if (!(ti == tj && qi > qj)) {
                KSS[N * Ng + M] = s;
                KSS[M * Ng + N] = s;
            }
        } else {
            g_KST[N * Ng + M] = s;
        }
    }
}

// ============================================================
// Kernel C: 1024-thread blocked (panel-8) solve -> g_alpha
// ============================================================
__global__ void __launch_bounds__(1024, 1)
solve_kernel(const float* __restrict__ yS,
             const float* __restrict__ KSS) {
    __shared__ float A[96 * 107];
    __shared__ float alphas[96 * 10];
    __shared__ float rtr_s;
    int t = threadIdx.x;
    int j = t & 127;
    int g = t >> 7;
    int row0 = g * 12;
    int w = t >> 5, lane = t & 31;

    for (int idx = t; idx < 96 * 96; idx += 1024) {
        int i = idx / 96, jj = idx - i * 96;
        A[i * 107 + jj] = KSS[idx];
    }
    for (int idx = t; idx < 960; idx += 1024) {
        int i = idx / 10, c = idx - i * 10;
        A[i * 107 + 96 + c] = yS[idx];
    }
    __syncthreads();

    if (t < 32) {
        float tr = 0.f;
        for (int i = t; i < 96; i += 32) tr += A[i * 107 + i];
        #pragma unroll
        for (int o = 16; o > 0; o >>= 1) tr += __shfl_down_sync(0xffffffffu, tr, o);
        if (t == 0) rtr_s = 1e-6f * tr / 96.f;
    }
    __syncthreads();
    if (t < 96) A[t * 107 + t] += rtr_s;
    __syncthreads();

    for (int p = 0; p < 12; p++) {
        int k0 = p * 8, pend = k0 + 7;

        if (w == 0) {
            for (int kk = 0; kk < 8; kk++) {
                int k = k0 + kk;
                float rp = __fdividef(1.f, A[k * 107 + k]);
                for (int i = k + 1 + lane; i < 96; i += 32) {
                    float f = A[i * 107 + k] * rp;
                    A[i * 107 + k] = f;
                    for (int q = kk + 1; q < 8; q++)
                        A[i * 107 + k0 + q] =
                            fmaf(-f, A[k * 107 + k0 + q], A[i * 107 + k0 + q]);
                }
                __syncwarp();
            }
        }
        __syncthreads();

        bool act = (j > pend) && (j < 107);
        float v[8];
        if (act) {
            #pragma unroll
            for (int q = 0; q < 8; q++) v[q] = A[(k0 + q) * 107 + j];
            #pragma unroll
            for (int q = 1; q < 8; q++)
                #pragma unroll
                for (int r = 0; r < 8; r++)
                    if (r < q)
                        v[q] = fmaf(-A[(k0 + q) * 107 + k0 + r], v[r], v[q]);
        }
        __syncthreads();

        if (act) {
            if (g == 0) {
                #pragma unroll
                for (int q = 0; q < 8; q++) A[(k0 + q) * 107 + j] = v[q];
            }
            int i0 = (row0 > pend) ? row0 : (pend + 1);
            int i1 = row0 + 12;
            for (int i = i0; i < i1; i++) {
                float a = A[i * 107 + j];
                #pragma unroll
                for (int q = 0; q < 8; q++)
                    a = fmaf(-A[i * 107 + k0 + q], v[q], a);
                A[i * 107 + j] = a;
            }
        }
        __syncthreads();
    }

    if (w == 0) {
        float r0[10], r1[10], r2[10];
        #pragma unroll
        for (int c = 0; c < 10; c++) {
            r0[c] = A[lane * 107 + 96 + c];
            r1[c] = A[(lane + 32) * 107 + 96 + c];
            r2[c] = A[(lane + 64) * 107 + 96 + c];
        }
        float al[10];
        for (int k = 95; k >= 64; k--) {
            int src = k & 31;
            float rp = __fdividef(1.f, A[k * 107 + k]);
            #pragma unroll
            for (int c = 0; c < 10; c++)
                al[c] = __shfl_sync(0xffffffffu, r2[c] * rp, src);
            if (lane == src) {
                #pragma unroll
                for (int c = 0; c < 10; c++) alphas[k * 10 + c] = al[c];
            }
            float L0 = A[lane * 107 + k];
            float L1 = A[(lane + 32) * 107 + k];
            #pragma unroll
            for (int c = 0; c < 10; c++) {
                r0[c] = fmaf(-L0, al[c], r0[c]);
                r1[c] = fmaf(-L1, al[c], r1[c]);
            }
            if (lane + 64 < k) {
                float L2 = A[(lane + 64) * 107 + k];
                #pragma unroll
                for (int c = 0; c < 10; c++) r2[c] = fmaf(-L2, al[c], r2[c]);
            }
        }
        for (int k = 63; k >= 32; k--) {
            int src = k & 31;
            float rp = __fdividef(1.f, A[k * 107 + k]);
            #pragma unroll
            for (int c = 0; c < 10; c++)
                al[c] = __shfl_sync(0xffffffffu, r1[c] * rp, src);
            if (lane == src) {
                #pragma unroll
                for (int c = 0; c < 10; c++) alphas[k * 10 + c] = al[c];
            }
            float L0 = A[lane * 107 + k];
            #pragma unroll
            for (int c = 0; c < 10; c++) r0[c] = fmaf(-L0, al[c], r0[c]);
            if (lane + 32 < k) {
                float L1 = A[(lane + 32) * 107 + k];
                #pragma unroll
                for (int c = 0; c < 10; c++) r1[c] = fmaf(-L1, al[c], r1[c]);
            }
        }
        for (int k = 31; k >= 0; k--) {
            float rp = __fdividef(1.f, A[k * 107 + k]);
            #pragma unroll
            for (int c = 0; c < 10; c++)
                al[c] = __shfl_sync(0xffffffffu, r0[c] * rp, k);
            if (lane == k) {
                #pragma unroll
                for (int c = 0; c < 10; c++) alphas[k * 10 + c] = al[c];
            }
            if (lane < k) {
                float L0 = A[lane * 107 + k];
                #pragma unroll
                for (int c = 0; c < 10; c++) r0[c] = fmaf(-L0, al[c], r0[c]);
            }
        }
    }
    __syncthreads();

    for (int idx = t; idx < 960; idx += 1024)
        g_alpha[idx] = alphas[idx];
}

// ============================================================
// Kernel D: pred with 4-way ILP
// ============================================================
__global__ void pred_kernel(float* __restrict__ out) {
    int idx = blockIdx.x * blockDim.x + threadIdx.x;
    if (idx >= 960) return;
    int cc = idx / 96, m = idx - cc * 96;
    float a0 = 0.f, a1 = 0.f, a2 = 0.f, a3 = 0.f;
    #pragma unroll 6
    for (int n = 0; n < 96; n += 4) {
        a0 = fmaf(g_KST[n * 96 + m],       g_alpha[n * 10 + cc],       a0);
        a1 = fmaf(g_KST[(n + 1) * 96 + m], g_alpha[(n + 1) * 10 + cc], a1);
        a2 = fmaf(g_KST[(n + 2) * 96 + m], g_alpha[(n + 2) * 10 + cc], a2);
        a3 = fmaf(g_KST[(n + 3) * 96 + m], g_alpha[(n + 3) * 10 + cc], a3);
    }
    out[m * 10 + cc] = (a0 + a1) + (a2 + a3);
}

// ============================================================
extern "C" void kernel_launch(void* const* d_in, const int* in_sizes, int n_in,
                              void* d_out, int out_size) {
    const float* U  = (const float*)d_in[0];
    const float* V  = (const float*)d_in[1];
    const float* XS = (const float*)d_in[2];
    const float* yS = (const float*)d_in[3];
    const float* AT = (const float*)d_in[4];
    const float* XT = (const float*)d_in[5];
    float* out = (float*)d_out;   // [pred (96,10) | K_SS (96,96)]
    float* KSS = out + Ng * Cc;

    cudaFuncSetAttribute(mma_tile_kernel, cudaFuncAttributeMaxDynamicSharedMemorySize,
                         SMEM_BYTES);

    cudaStream_t s2 = g_res.s2;

    precompute_kernel<<<Ng, 128>>>(U, V, XS, AT, XT);
    mma_tile_kernel<<<NSS, TPB, SMEM_BYTES>>>(KSS, 0);

    // fork: solve on s2 (needs only KSS), ST tiles continue on default
    cudaEventRecord(g_res.evSS, 0);
    cudaStreamWaitEvent(s2, g_res.evSS, 0);
    solve_kernel<<<1, 1024, 0, s2>>>(yS, KSS);
    cudaEventRecord(g_res.evSolve, s2);

    mma_tile_kernel<<<NST, TPB, SMEM_BYTES>>>(KSS, 1);

    // join: pred needs ST (default) + solve (s2)
    cudaStreamWaitEvent(0, g_res.evSolve, 0);
    pred_kernel<<<8, 128>>>(out);
}

// round 15
// speedup vs baseline: 1.1995x; 1.1995x over previous
#include <cuda_runtime.h>
#include <cuda_bf16.h>
#include <math.h>
#include <stdint.h>

#define Ng 96
#define nS 48
#define RK 16
#define Dd 128
#define Cc 10
#define NSS 1176   // 48*49/2 graph-pair tiles (2x2 graphs per tile)
#define NST 2304   // 48*48

// tile-kernel smem layout in u32 units
#define LDU 68
#define LDB 272
#define AH_U 0
#define AL_U (96 * LDU)
#define BH_U (2 * 96 * LDU)
#define BL_U (3 * 96 * LDU)
#define DV_U (4 * 96 * LDU)          // 6 x 96 floats: eA,A1,A2,eB,B1,B2
#define WS_U (DV_U + 576)
#define SMEM_U32 (WS_U + 8)
#define SMEM_BYTES (SMEM_U32 * 4)

// ---------- persistent scratch ----------
__device__ float g_es[Ng * nS];   // 0.01 / d0S
__device__ float g_wd[Ng * nS];   // w * d0S
__device__ float g_w[Ng * nS];    // w
__device__ float g_et[Ng * nS];   // 0.01 / d0T
__device__ float g_zd[Ng * nS];   // z * d0T
__device__ float g_z[Ng * nS];    // z
__device__ float g_KST[Ng * Ng];
__device__ float g_alpha[Ng * Cc];
__device__ __nv_bfloat16 g_Shi[Ng * nS * Dd];   // normalized x/d0, hi
__device__ __nv_bfloat16 g_Slo[Ng * nS * Dd];
__device__ __nv_bfloat16 g_Thi[Ng * nS * Dd];
__device__ __nv_bfloat16 g_Tlo[Ng * nS * Dd];

// ---------- streams/events (static init) ----------
namespace {
struct GpuRes {
    cudaStream_t s2;
    cudaEvent_t evSS, evSolve;
    GpuRes() {
        cudaStreamCreateWithFlags(&s2, cudaStreamNonBlocking);
        cudaEventCreateWithFlags(&evSS, cudaEventDisableTiming);
        cudaEventCreateWithFlags(&evSolve, cudaEventDisableTiming);
    }
};
GpuRes g_res;
}

// ---------- mma.sync m16n8k16 bf16 ----------
__device__ __forceinline__ void mma16816(float* c, const uint32_t* a,
                                         uint32_t b0, uint32_t b1) {
    asm volatile(
        "mma.sync.aligned.m16n8k16.row.col.f32.bf16.bf16.f32 "
        "{%0,%1,%2,%3}, {%4,%5,%6,%7}, {%8,%9}, {%0,%1,%2,%3};"
        : "+f"(c[0]), "+f"(c[1]), "+f"(c[2]), "+f"(c[3])
        : "r"(a[0]), "r"(a[1]), "r"(a[2]), "r"(a[3]), "r"(b0), "r"(b1));
}
__device__ __forceinline__ void ldmx4(uint32_t* r, uint32_t addr) {
    asm volatile("ldmatrix.sync.aligned.m8n8.x4.shared.b16 {%0,%1,%2,%3}, [%4];"
                 : "=r"(r[0]), "=r"(r[1]), "=r"(r[2]), "=r"(r[3]) : "r"(addr));
}
__device__ __forceinline__ void ldmx2(uint32_t* r, uint32_t addr) {
    asm volatile("ldmatrix.sync.aligned.m8n8.x2.shared.b16 {%0,%1}, [%2];"
                 : "=r"(r[0]), "=r"(r[1]) : "r"(addr));
}
__device__ __forceinline__ uint32_t smem_u32(const void* p) {
    uint32_t a;
    asm("{ .reg .u64 t; cvta.to.shared.u64 t, %1; cvt.u32.u64 %0, t; }"
        : "=r"(a) : "l"(p));
    return a;
}

// ---------- fast NTK (normalized form; acos poly A&S 4.4.46) ----------
__device__ __forceinline__ float acos_pos(float ax, float u) {
    float p = fmaf(ax, -0.0012624911f, 0.0066700901f);
    p = fmaf(ax, p, -0.0170881256f);
    p = fmaf(ax, p, 0.0308918810f);
    p = fmaf(ax, p, -0.0501743046f);
    p = fmaf(ax, p, 0.0889789874f);
    p = fmaf(ax, p, -0.2145988016f);
    p = fmaf(ax, p, 1.5707963050f);
    return u * p;
}

__device__ __forceinline__ float ntk_acc(float p, float dot, float ea, float eb,
                                         float ab1, float ab2, float ic1) {
    const float PI_F = 3.14159265358979323846f;
    const float IPI = 0.318309886183790672f;
    float sir = fmaf(ea, eb, dot);
    float si = fminf(fmaxf(sir, -0.9999f), 0.9999f);
    float ax = fabsf(si);
    float u = sqrtf(1.f - ax);
    float vq = sqrtf(1.f + ax);
    float thp = acos_pos(ax, u);
    float pit = (si < 0.f) ? thp : (PI_F - thp);
    float D1 = pit * IPI;
    float s1 = fmaf(si, pit, u * vq) * IPI;
    float si2 = fminf(s1 * ic1, 0.9999f);
    float u2 = sqrtf(1.f - si2);
    float v2 = sqrtf(1.f + si2);
    float pit2 = PI_F - acos_pos(si2, u2);
    float D2 = pit2 * IPI;
    float s2v = fmaf(si2, pit2, u2 * v2) * IPI;
    p = fmaf(ab1 * sir, D1 * D2, p);
    p = fmaf(ab2, fmaf(s1, D2, s2v), p);
    return p;
}

// ============================================================
// Kernel A: per-graph precompute
// ============================================================
__global__ void precompute_kernel(const float* __restrict__ U,
                                  const float* __restrict__ V,
                                  const float* __restrict__ XS,
                                  const float* __restrict__ AT,
                                  const float* __restrict__ XT) {
    int g = blockIdx.x, t = threadIdx.x;
    __shared__ float sU[nS * RK];
    __shared__ float sV[RK * nS];
    __shared__ float sA[nS * nS];
    __shared__ float VU[RK][RK];
    __shared__ float u1[RK], u2a[RK], u2[RK], sv[nS];
    __shared__ float d0s[nS], d0t[nS], invs[nS], invt[nS];

    const float4* Up = (const float4*)(U + (size_t)g * nS * RK);
    const float4* Vp = (const float4*)(V + (size_t)g * RK * nS);
    const float4* Ap = (const float4*)(AT + (size_t)g * nS * nS);
    for (int i = t; i < 192; i += 128) ((float4*)sU)[i] = Up[i];
    for (int i = t; i < 192; i += 128) ((float4*)sV)[i] = Vp[i];
    for (int i = t; i < 576; i += 128) ((float4*)sA)[i] = Ap[i];

    const float* xs = XS + (size_t)g * nS * Dd;
    const float* xt = XT + (size_t)g * nS * Dd;
    if (t < nS) {
        const float4* row = (const float4*)(xs + t * Dd);
        float acc = 0.f;
        #pragma unroll
        for (int k = 0; k < Dd / 4; k++) {
            float4 v = row[k];
            acc += v.x * v.x + v.y * v.y + v.z * v.z + v.w * v.w;
        }
        float d = sqrtf(acc + 1e-4f);
        d0s[t] = d;
        invs[t] = 1.f / d;
    } else if (t < 2 * nS) {
        int r = t - nS;
        const float4* row = (const float4*)(xt + r * Dd);
        float acc = 0.f;
        #pragma unroll
        for (int k = 0; k < Dd / 4; k++) {
            float4 v = row[k];
            acc += v.x * v.x + v.y * v.y + v.z * v.z + v.w * v.w;
        }
        float d = sqrtf(acc + 1e-4f);
        d0t[r] = d;
        invt[r] = 1.f / d;
    }
    __syncthreads();

    {
        const float4* xs4 = (const float4*)xs;
        const float4* xt4 = (const float4*)xt;
        size_t base = (size_t)g * nS * Dd / 4;
        for (int i = t; i < nS * 32; i += 128) {
            int row = i >> 5;
            float4 a = xs4[i];
            float is = invs[row];
            __nv_bfloat16 hh[4], ll[4];
            float av[4] = {a.x * is, a.y * is, a.z * is, a.w * is};
            #pragma unroll
            for (int e = 0; e < 4; e++) {
                __nv_bfloat16 h = __float2bfloat16(av[e]);
                hh[e] = h;
                ll[e] = __float2bfloat16(av[e] - __bfloat162float(h));
            }
            ((uint2*)g_Shi)[base + i] = *(uint2*)hh;
            ((uint2*)g_Slo)[base + i] = *(uint2*)ll;

            float4 b = xt4[i];
            float it = invt[row];
            float bv[4] = {b.x * it, b.y * it, b.z * it, b.w * it};
            #pragma unroll
            for (int e = 0; e < 4; e++) {
                __nv_bfloat16 h = __float2bfloat16(bv[e]);
                hh[e] = h;
                ll[e] = __float2bfloat16(bv[e] - __bfloat162float(h));
            }
            ((uint2*)g_Thi)[base + i] = *(uint2*)hh;
            ((uint2*)g_Tlo)[base + i] = *(uint2*)ll;
        }
    }
    __syncthreads();

    for (int e = t; e < RK * RK; e += 128) {
        int i = e >> 4, jj = e & 15;
        float acc = 0.f;
        #pragma unroll 8
        for (int a = 0; a < nS; a++) acc += sV[i * nS + a] * sU[a * RK + jj];
        VU[i][jj] = acc;
    }
    if (t < RK) {
        float acc = 0.f;
        #pragma unroll 8
        for (int a = 0; a < nS; a++) acc += sU[a * RK + t];
        u1[t] = acc;
    } else if (t >= 32 && t < 32 + nS) {
        int i = t - 32;
        float acc = 0.f;
        #pragma unroll 8
        for (int jj = 0; jj < nS; jj++) acc += sA[jj * nS + i];
        sv[i] = acc + 1e-4f;
    }
    __syncthreads();
    if (t < RK) {
        float acc = 0.f;
        #pragma unroll
        for (int r = 0; r < RK; r++) acc += VU[r][t] * u1[r];
        u2a[t] = acc;
    }
    __syncthreads();
    if (t < RK) {
        float acc = 0.f;
        #pragma unroll
        for (int r = 0; r < RK; r++) acc += VU[r][t] * u2a[r];
        u2[t] = acc;
    }
    __syncthreads();
    if (t < nS) {
        float acc = 0.f;
        #pragma unroll
        for (int r = 0; r < RK; r++) acc += sV[r * nS + t] * u2[r];
        g_w[g * nS + t] = acc;
        g_wd[g * nS + t] = acc * d0s[t];
        g_es[g * nS + t] = 0.01f * invs[t];
    } else if (t < 2 * nS) {
        int i = t - nS;
        float acc = 0.f;
        #pragma unroll 8
        for (int jj = 0; jj < nS; jj++) acc += sA[jj * nS + i] * sv[jj];
        float z = acc + 1e-4f * sv[i];
        g_z[g * nS + i] = z;
        g_zd[g * nS + i] = z * d0t[i];
        g_et[g * nS + i] = 0.01f * invt[i];
    }
}

// ============================================================
// Kernel B: HMMA tile kernel, 256 threads (8 warps, 2x4).
// Fused split mainloop: load Ah/Al/Bh/Bl fragments ONCE per kstep
// and issue all 27 MMAs from registers (36 wf vs 54 wf per warp-kstep).
// ============================================================
__global__ void __launch_bounds__(256, 2)
mma_tile_kernel(float* __restrict__ KSS, int mode) {
    extern __shared__ uint32_t smU[];
    int bid = blockIdx.x;

    int ti, tj, isST = mode;
    if (!mode) {
        int rem = bid, cnt = 48;
        ti = 0;
        while (rem >= cnt) { rem -= cnt; ti++; cnt--; }
        tj = ti + rem;
    } else {
        ti = bid / 48;
        tj = bid - ti * 48;
    }

    uint32_t sbase = smem_u32(smU);
    int t = threadIdx.x;
    int w = t >> 5, lane = t & 31;
    int g2 = lane >> 2, tg = lane & 3;

    const uint4* ShiV = (const uint4*)g_Shi;
    const uint4* SloV = (const uint4*)g_Slo;
    const uint4* RhiV = isST ? (const uint4*)g_Thi : ShiV;
    const uint4* RloV = isST ? (const uint4*)g_Tlo : SloV;
    int rowL = ti * 96, rowR = tj * 96;

    for (int idx = t; idx < 96 * 16; idx += 256) {
        int r = idx >> 4, c4 = idx & 15;
        int so = r * LDU + c4 * 4;
        *(uint4*)(smU + AH_U + so) = ShiV[(size_t)(rowL + r) * 16 + c4];
        *(uint4*)(smU + AL_U + so) = SloV[(size_t)(rowL + r) * 16 + c4];
        *(uint4*)(smU + BH_U + so) = RhiV[(size_t)(rowR + r) * 16 + c4];
        *(uint4*)(smU + BL_U + so) = RloV[(size_t)(rowR + r) * 16 + c4];
    }
    float* dv = (float*)(smU + DV_U);
    if (t < 96) {
        dv[t] = g_es[rowL + t];
        dv[96 + t] = g_wd[rowL + t];
        dv[192 + t] = g_w[rowL + t];
    } else if (t < 192) {
        int r = t - 96;
        dv[288 + r] = (isST ? g_et : g_es)[rowR + r];
        dv[384 + r] = (isST ? g_zd : g_wd)[rowR + r];
        dv[480 + r] = (isST ? g_z : g_w)[rowR + r];
    }
    __syncthreads();

    int wr = w >> 2, wc = w & 3;
    int mrow0 = wr * 48, ncol0 = wc * 24;

    int l7 = lane & 7;
    uint32_t aoff = (uint32_t)((mrow0 + l7 + ((lane >> 3) & 1) * 8) * LDB +
                               ((lane >> 4) & 1) * 16);
    uint32_t boff01 = (uint32_t)((ncol0 + ((lane >> 4) & 1) * 8 + l7) * LDB +
                                 ((lane >> 3) & 1) * 16);
    uint32_t boff2 = (uint32_t)((ncol0 + 16 + l7) * LDB +
                                ((lane >> 3) & 1) * 16);

    uint32_t AhB = sbase + (uint32_t)(AH_U * 4);
    uint32_t AlB = sbase + (uint32_t)(AL_U * 4);
    uint32_t BhB = sbase + (uint32_t)(BH_U * 4);
    uint32_t BlB = sbase + (uint32_t)(BL_U * 4);

    float acc[3][3][4];
    #pragma unroll
    for (int mi = 0; mi < 3; mi++)
        #pragma unroll
        for (int nj = 0; nj < 3; nj++)
            #pragma unroll
            for (int e = 0; e < 4; e++) acc[mi][nj][e] = 0.f;

    #pragma unroll
    for (int ks = 0; ks < 8; ks++) {
        uint32_t kb = (uint32_t)(ks * 32);
        uint32_t bh01[4], bh2[2], bl01[4], bl2[2];
        ldmx4(bh01, BhB + boff01 + kb);
        ldmx2(bh2, BhB + boff2 + kb);
        ldmx4(bl01, BlB + boff01 + kb);
        ldmx2(bl2, BlB + boff2 + kb);
        #pragma unroll
        for (int mi = 0; mi < 3; mi++) {
            uint32_t moff = aoff + (uint32_t)(mi * 16 * LDB) + kb;
            uint32_t ah[4], al[4];
            ldmx4(ah, AhB + moff);
            ldmx4(al, AlB + moff);
            // Ah*Bh
            mma16816(acc[mi][0], ah, bh01[0], bh01[1]);
            mma16816(acc[mi][1], ah, bh01[2], bh01[3]);
            mma16816(acc[mi][2], ah, bh2[0], bh2[1]);
            // Ah*Bl
            mma16816(acc[mi][0], ah, bl01[0], bl01[1]);
            mma16816(acc[mi][1], ah, bl01[2], bl01[3]);
            mma16816(acc[mi][2], ah, bl2[0], bl2[1]);
            // Al*Bh
            mma16816(acc[mi][0], al, bh01[0], bh01[1]);
            mma16816(acc[mi][1], al, bh01[2], bh01[3]);
            mma16816(acc[mi][2], al, bh2[0], bh2[1]);
        }
    }

    const float PI_F = 3.14159265358979323846f;
    float thc = acosf(0.9999f);
    float c1 = (0.9999f * (PI_F - thc) + sqrtf(1.f - 0.9999f * 0.9999f)) / PI_F;
    float ic1 = 1.f / c1;

    const float* sEa = dv;
    const float* sA1 = dv + 96;
    const float* sA2 = dv + 192;
    const float* sEb = dv + 288;
    const float* sB1 = dv + 384;
    const float* sB2 = dv + 480;

    float partial = 0.f;
    #pragma unroll
    for (int mi = 0; mi < 3; mi++) {
        int r0 = mrow0 + mi * 16 + g2, r1 = r0 + 8;
        float ea0 = sEa[r0], a10 = sA1[r0], a20 = sA2[r0];
        float ea1 = sEa[r1], a11 = sA1[r1], a21 = sA2[r1];
        #pragma unroll
        for (int nj = 0; nj < 3; nj++) {
            int c0 = ncol0 + nj * 8 + tg * 2, c1i = c0 + 1;
            float eb0 = sEb[c0], b10 = sB1[c0], b20 = sB2[c0];
            float eb1 = sEb[c1i], b11 = sB1[c1i], b21 = sB2[c1i];
            partial = ntk_acc(partial, acc[mi][nj][0], ea0, eb0, a10 * b10, a20 * b20, ic1);
            partial = ntk_acc(partial, acc[mi][nj][1], ea0, eb1, a10 * b11, a20 * b21, ic1);
            partial = ntk_acc(partial, acc[mi][nj][2], ea1, eb0, a11 * b10, a21 * b20, ic1);
            partial = ntk_acc(partial, acc[mi][nj][3], ea1, eb1, a11 * b11, a21 * b21, ic1);
        }
    }

    #pragma unroll
    for (int o = 16; o > 0; o >>= 1)
        partial += __shfl_down_sync(0xffffffffu, partial, o);
    float* wslot = (float*)(smU + WS_U);
    if (lane == 0) wslot[w] = partial;
    __syncthreads();

    if (t < 4) {
        int qi = t >> 1, qj = t & 1;
        int w0 = qi * 4 + qj * 2;
        float s = wslot[w0] + wslot[w0 + 1];
        int N = 2 * ti + qi, M = 2 * tj + qj;
        if (!isST) {
            if (!(ti == tj && qi > qj)) {
                KSS[N * Ng + M] = s;
                KSS[M * Ng + N] = s;
            }
        } else {
            g_KST[N * Ng + M] = s;
        }
    }
}

// ============================================================
// Kernel C: 1024-thread blocked (panel-8) solve -> g_alpha
// ============================================================
__global__ void __launch_bounds__(1024, 1)
solve_kernel(const float* __restrict__ yS,
             const float* __restrict__ KSS) {
    __shared__ float A[96 * 107];
    __shared__ float alphas[96 * 10];
    __shared__ float rtr_s;
    int t = threadIdx.x;
    int j = t & 127;
    int g = t >> 7;
    int row0 = g * 12;
    int w = t >> 5, lane = t & 31;

    for (int idx = t; idx < 96 * 96; idx += 1024) {
        int i = idx / 96, jj = idx - i * 96;
        A[i * 107 + jj] = KSS[idx];
    }
    for (int idx = t; idx < 960; idx += 1024) {
        int i = idx / 10, c = idx - i * 10;
        A[i * 107 + 96 + c] = yS[idx];
    }
    __syncthreads();

    if (t < 32) {
        float tr = 0.f;
        for (int i = t; i < 96; i += 32) tr += A[i * 107 + i];
        #pragma unroll
        for (int o = 16; o > 0; o >>= 1) tr += __shfl_down_sync(0xffffffffu, tr, o);
        if (t == 0) rtr_s = 1e-6f * tr / 96.f;
    }
    __syncthreads();
    if (t < 96) A[t * 107 + t] += rtr_s;
    __syncthreads();

    for (int p = 0; p < 12; p++) {
        int k0 = p * 8, pend = k0 + 7;

        if (w == 0) {
            for (int kk = 0; kk < 8; kk++) {
                int k = k0 + kk;
                float rp = __fdividef(1.f, A[k * 107 + k]);
                for (int i = k + 1 + lane; i < 96; i += 32) {
                    float f = A[i * 107 + k] * rp;
                    A[i * 107 + k] = f;
                    for (int q = kk + 1; q < 8; q++)
                        A[i * 107 + k0 + q] =
                            fmaf(-f, A[k * 107 + k0 + q], A[i * 107 + k0 + q]);
                }
                __syncwarp();
            }
        }
        __syncthreads();

        bool act = (j > pend) && (j < 107);
        float v[8];
        if (act) {
            #pragma unroll
            for (int q = 0; q < 8; q++) v[q] = A[(k0 + q) * 107 + j];
            #pragma unroll
            for (int q = 1; q < 8; q++)
                #pragma unroll
                for (int r = 0; r < 8; r++)
                    if (r < q)
                        v[q] = fmaf(-A[(k0 + q) * 107 + k0 + r], v[r], v[q]);
        }
        __syncthreads();

        if (act) {
            if (g == 0) {
                #pragma unroll
                for (int q = 0; q < 8; q++) A[(k0 + q) * 107 + j] = v[q];
            }
            int i0 = (row0 > pend) ? row0 : (pend + 1);
            int i1 = row0 + 12;
            for (int i = i0; i < i1; i++) {
                float a = A[i * 107 + j];
                #pragma unroll
                for (int q = 0; q < 8; q++)
                    a = fmaf(-A[i * 107 + k0 + q], v[q], a);
                A[i * 107 + j] = a;
            }
        }
        __syncthreads();
    }

    if (w == 0) {
        float r0[10], r1[10], r2[10];
        #pragma unroll
        for (int c = 0; c < 10; c++) {
            r0[c] = A[lane * 107 + 96 + c];
            r1[c] = A[(lane + 32) * 107 + 96 + c];
            r2[c] = A[(lane + 64) * 107 + 96 + c];
        }
        float al[10];
        for (int k = 95; k >= 64; k--) {
            int src = k & 31;
            float rp = __fdividef(1.f, A[k * 107 + k]);
            #pragma unroll
            for (int c = 0; c < 10; c++)
                al[c] = __shfl_sync(0xffffffffu, r2[c] * rp, src);
            if (lane == src) {
                #pragma unroll
                for (int c = 0; c < 10; c++) alphas[k * 10 + c] = al[c];
            }
            float L0 = A[lane * 107 + k];
            float L1 = A[(lane + 32) * 107 + k];
            #pragma unroll
            for (int c = 0; c < 10; c++) {
                r0[c] = fmaf(-L0, al[c], r0[c]);
                r1[c] = fmaf(-L1, al[c], r1[c]);
            }
            if (lane + 64 < k) {
                float L2 = A[(lane + 64) * 107 + k];
                #pragma unroll
                for (int c = 0; c < 10; c++) r2[c] = fmaf(-L2, al[c], r2[c]);
            }
        }
        for (int k = 63; k >= 32; k--) {
            int src = k & 31;
            float rp = __fdividef(1.f, A[k * 107 + k]);
            #pragma unroll
            for (int c = 0; c < 10; c++)
                al[c] = __shfl_sync(0xffffffffu, r1[c] * rp, src);
            if (lane == src) {
                #pragma unroll
                for (int c = 0; c < 10; c++) alphas[k * 10 + c] = al[c];
            }
            float L0 = A[lane * 107 + k];
            #pragma unroll
            for (int c = 0; c < 10; c++) r0[c] = fmaf(-L0, al[c], r0[c]);
            if (lane + 32 < k) {
                float L1 = A[(lane + 32) * 107 + k];
                #pragma unroll
                for (int c = 0; c < 10; c++) r1[c] = fmaf(-L1, al[c], r1[c]);
            }
        }
        for (int k = 31; k >= 0; k--) {
            float rp = __fdividef(1.f, A[k * 107 + k]);
            #pragma unroll
            for (int c = 0; c < 10; c++)
                al[c] = __shfl_sync(0xffffffffu, r0[c] * rp, k);
            if (lane == k) {
                #pragma unroll
                for (int c = 0; c < 10; c++) alphas[k * 10 + c] = al[c];
            }
            if (lane < k) {
                float L0 = A[lane * 107 + k];
                #pragma unroll
                for (int c = 0; c < 10; c++) r0[c] = fmaf(-L0, al[c], r0[c]);
            }
        }
    }
    __syncthreads();

    for (int idx = t; idx < 960; idx += 1024)
        g_alpha[idx] = alphas[idx];
}

// ============================================================
// Kernel D: pred with 4-way ILP
// ============================================================
__global__ void pred_kernel(float* __restrict__ out) {
    int idx = blockIdx.x * blockDim.x + threadIdx.x;
    if (idx >= 960) return;
    int cc = idx / 96, m = idx - cc * 96;
    float a0 = 0.f, a1 = 0.f, a2 = 0.f, a3 = 0.f;
    #pragma unroll 6
    for (int n = 0; n < 96; n += 4) {
        a0 = fmaf(g_KST[n * 96 + m],       g_alpha[n * 10 + cc],       a0);
        a1 = fmaf(g_KST[(n + 1) * 96 + m], g_alpha[(n + 1) * 10 + cc], a1);
        a2 = fmaf(g_KST[(n + 2) * 96 + m], g_alpha[(n + 2) * 10 + cc], a2);
        a3 = fmaf(g_KST[(n + 3) * 96 + m], g_alpha[(n + 3) * 10 + cc], a3);
    }
    out[m * 10 + cc] = (a0 + a1) + (a2 + a3);
}

// ============================================================
extern "C" void kernel_launch(void* const* d_in, const int* in_sizes, int n_in,
                              void* d_out, int out_size) {
    const float* U  = (const float*)d_in[0];
    const float* V  = (const float*)d_in[1];
    const float* XS = (const float*)d_in[2];
    const float* yS = (const float*)d_in[3];
    const float* AT = (const float*)d_in[4];
    const float* XT = (const float*)d_in[5];
    float* out = (float*)d_out;   // [pred (96,10) | K_SS (96,96)]
    float* KSS = out + Ng * Cc;

    cudaFuncSetAttribute(mma_tile_kernel, cudaFuncAttributeMaxDynamicSharedMemorySize,
                         SMEM_BYTES);

    cudaStream_t s2 = g_res.s2;

    precompute_kernel<<<Ng, 128>>>(U, V, XS, AT, XT);
    mma_tile_kernel<<<NSS, 256, SMEM_BYTES>>>(KSS, 0);

    // fork: solve on s2 (needs only KSS), ST tiles continue on default
    cudaEventRecord(g_res.evSS, 0);
    cudaStreamWaitEvent(s2, g_res.evSS, 0);
    solve_kernel<<<1, 1024, 0, s2>>>(yS, KSS);
    cudaEventRecord(g_res.evSolve, s2);

    mma_tile_kernel<<<NST, 256, SMEM_BYTES>>>(KSS, 1);

    // join: pred needs ST (default) + solve (s2)
    cudaStreamWaitEvent(0, g_res.evSolve, 0);
    pred_kernel<<<8, 128>>>(out);
}